// round 12
// baseline (speedup 1.0000x reference)
#include <cuda_runtime.h>
#include <cuda_bf16.h>
#include <stdint.h>
#include <math.h>

// ESN: B=64, T=256, I=128, R=2048, O=10, alpha=0.5
#define BB 64
#define TT 256
#define II 128
#define RR 2048
#define OO 10
#define NCTA 128
#define NTHR 256

// ---------------- device globals ----------------
__device__ __align__(256) __nv_bfloat16 g_reshi[BB * RR];
__device__ __align__(256) __nv_bfloat16 g_reslo[BB * RR];
__device__ __align__(256) float g_part[8 * 16 * BB * 128];  // [ks][mt][b][jr]
__device__ __align__(128) unsigned g_cnt;            // global barrier counter
__device__ __align__(128) unsigned g_cnt1[16 * 32];  // per-mt, 128B apart

// ---------------- smem layout (bytes) ----------------
#define ROWB 528
#define SM_A_HI 0
#define SM_A_LO (128 * ROWB)            // 67584
#define SM_R_HI (2 * 128 * ROWB)        // 135168 (scan: res hi; also sP)
#define SM_R_LO (SM_R_HI + 64 * ROWB)   // 168960 (scan: res lo)
#define SM_TOTAL (SM_R_LO + 64 * ROWB)  // 202752

// ---------------- helpers ----------------
static __device__ __forceinline__ unsigned long long dup2(float v) {
    unsigned long long r;
    unsigned u = __float_as_uint(v);
    asm("mov.b64 %0, {%1, %1};" : "=l"(r) : "r"(u));
    return r;
}
static __device__ __forceinline__ void fma2(unsigned long long& a,
                                            unsigned long long x,
                                            unsigned long long y) {
    asm("fma.rn.f32x2 %0, %1, %2, %0;" : "+l"(a) : "l"(x), "l"(y));
}
static __device__ __forceinline__ float lo32(unsigned long long a) {
    return __uint_as_float((unsigned)a);
}
static __device__ __forceinline__ float hi32(unsigned long long a) {
    return __uint_as_float((unsigned)(a >> 32));
}
static __device__ __forceinline__ void mma_bf16(float* d, const unsigned* a,
                                                const unsigned* b) {
    asm volatile(
        "mma.sync.aligned.m16n8k16.row.col.f32.bf16.bf16.f32 "
        "{%0,%1,%2,%3}, {%4,%5,%6,%7}, {%8,%9}, {%0,%1,%2,%3};"
        : "+f"(d[0]), "+f"(d[1]), "+f"(d[2]), "+f"(d[3])
        : "r"(a[0]), "r"(a[1]), "r"(a[2]), "r"(a[3]), "r"(b[0]), "r"(b[1]));
}
static __device__ __forceinline__ void arrive(unsigned* ctr) {
    asm volatile("red.release.gpu.global.add.u32 [%0], 1;" ::"l"(ctr)
                 : "memory");
}
static __device__ __forceinline__ void waitctr(unsigned* ctr, unsigned target,
                                               int slow) {
    unsigned v;
    int spins = 0;
    for (;;) {
        asm volatile("ld.relaxed.gpu.global.u32 %0, [%1];"
                     : "=r"(v)
                     : "l"(ctr));
        if ((int)(v - target) >= 0) break;
        if (++spins > (slow ? 2 : 64)) __nanosleep(40);
    }
    asm volatile("ld.acquire.gpu.global.u32 %0, [%1];" : "=r"(v) : "l"(ctr));
}
static __device__ __forceinline__ unsigned pk(float a, float b) {
    __nv_bfloat162 h = __floats2bfloat162_rn(a, b);
    return *(unsigned*)&h;
}

extern "C" __global__ void __launch_bounds__(NTHR, 1)
esn_mma(const float* __restrict__ x, const float* __restrict__ i2h,
        const float* __restrict__ h2h, const float* __restrict__ ow,
        const float* __restrict__ ob, float* __restrict__ out,
        float* __restrict__ hid) {
    extern __shared__ char sm8[];
    const int tid = threadIdx.x;
    const int cta = blockIdx.x;
    const int mt = cta & 15;  // j block of 128
    const int ks = cta >> 4;  // k block of 256

    // replay-safe counter bases (mask to per-launch totals: both powers of 2)
    unsigned barBase, c1Base;
    {
        unsigned v;
        asm volatile("ld.relaxed.gpu.global.u32 %0, [%1];"
                     : "=r"(v)
                     : "l"(&g_cnt));
        barBase = v & ~(unsigned)(256 * NCTA - 1);  // 32768/launch
        asm volatile("ld.relaxed.gpu.global.u32 %0, [%1];"
                     : "=r"(v)
                     : "l"(&g_cnt1[mt * 32]));
        c1Base = v & ~2047u;  // 8*256/launch
    }

    // ===== Phase 0: transpose own h2h tiles straight into persistent sA ===
    // CTA consumes A rows j=mt*128..+128, cols k=ks*256..+256 == transposes
    // of source tiles (ti=2ks+rep, tj=mt).
    {
        float* sT = (float*)(sm8 + SM_R_HI);  // 128x131 fp32 (67072B, fits)
        for (int rep = 0; rep < 2; rep++) {
            int ti = 2 * ks + rep;
            __syncthreads();
            for (int idx = tid; idx < 16384; idx += NTHR) {
                int r = idx >> 7, c = idx & 127;
                sT[r * 131 + c] = h2h[(ti * 128 + r) * RR + mt * 128 + c];
            }
            __syncthreads();
            for (int idx = tid; idx < 16384; idx += NTHR) {
                int jl = idx >> 7, kl = idx & 127;
                float v = sT[kl * 131 + jl];  // transpose read (131: no bank
                                              // conflicts, gcd(3,32)=1)
                __nv_bfloat16 bhi = __float2bfloat16_rn(v);
                __nv_bfloat16 blo =
                    __float2bfloat16_rn(v - __bfloat162float(bhi));
                uint32_t off = (uint32_t)jl * ROWB + (rep * 128 + kl) * 2;
                *(__nv_bfloat16*)(sm8 + SM_A_HI + off) = bhi;
                *(__nv_bfloat16*)(sm8 + SM_A_LO + off) = blo;
            }
        }
        __syncthreads();
    }

    // ===== Phase A: xin = x @ i2h for own (self-consumed) 16-col slice ====
    const int j0c = mt * 128 + ks * 16;
    {
        float* sX = (float*)(sm8 + SM_R_HI);  // [64][132] fp32
        float* si = (float*)(sm8 + SM_R_LO);  // [128][16] fp32
        for (int i = tid; i < II * 16; i += NTHR) {
            int k = i >> 4, jj = i & 15;
            si[i] = i2h[k * RR + j0c + jj];
        }
        const int row = tid >> 2;
        const int jq = tid & 3;
        for (int rt = 0; rt < BB * TT; rt += 64) {
            __syncthreads();
            for (int i = tid; i < 64 * II / 4; i += NTHR) {
                int r = i >> 5, q = i & 31;
                *(float4*)&sX[r * 132 + q * 4] =
                    *(const float4*)&x[(rt + r) * II + q * 4];
            }
            __syncthreads();
            unsigned long long a0 = 0ull, a1 = 0ull;
#pragma unroll 8
            for (int k = 0; k < II; k++) {
                unsigned long long xv = dup2(sX[row * 132 + k]);
                ulonglong2 hv = *(const ulonglong2*)&si[k * 16 + jq * 4];
                fma2(a0, xv, hv.x);
                fma2(a1, xv, hv.y);
            }
            float4 o = make_float4(lo32(a0), hi32(a0), lo32(a1), hi32(a1));
            *(float4*)&hid[(rt + row) * RR + j0c + jq * 4] = o;
        }
        __syncthreads();
    }

    // =========== Scan ===========
    const int w = tid >> 5;
    const int l = tid & 31;
    const int g = l >> 2, tg = l & 3;
    const int mw = w & 3;             // m-pair: jr rows 32mw..32mw+31
    const int nh = w >> 2;            // n-half: b cols 32nh..32nh+31
    const int tidh = tid - nh * 128;  // 0..127 within half
    // epilogue: thread owns (eb = tid>>2, j0e = j0c + (tid&3)*4)
    const int eb = tid >> 2;
    const int ejq = tid & 3;
    const int j0e = j0c + ejq * 4;
    float4 p0 = make_float4(0.f, 0.f, 0.f, 0.f);
    float4 pend;

    const char* sAhi = sm8 + SM_A_HI;
    const char* sAlo = sm8 + SM_A_LO;
    const char* sRhi = sm8 + SM_R_HI;
    const char* sRlo = sm8 + SM_R_LO;
    float* sP = (float*)(sm8 + SM_R_HI);  // [64][132] partial bounce
    const int pbase = (ks * 16 + mt) * 64;
    unsigned* cnt1 = &g_cnt1[mt * 32];

    for (int t = 0; t < TT; t++) {
        float4 xv;
        float4 q = make_float4(0.f, 0.f, 0.f, 0.f);
        if (t > 0) {
            // stage res tile [64][256] hi/lo from global
            for (int idx = tid; idx < 2048; idx += NTHR) {
                int row = idx >> 5, kc = idx & 31;
                *(uint4*)(sm8 + SM_R_HI + row * ROWB + kc * 16) =
                    *(const uint4*)&g_reshi[row * RR + ks * 256 + kc * 8];
                *(uint4*)(sm8 + SM_R_LO + row * ROWB + kc * 16) =
                    *(const uint4*)&g_reslo[row * RR + ks * 256 + kc * 8];
            }
            *(float4*)&hid[(eb * TT + (t - 1)) * RR + j0e] = pend;
            __syncthreads();
            float acc[2][4][4];
#pragma unroll
            for (int mi = 0; mi < 2; mi++)
#pragma unroll
                for (int ni = 0; ni < 4; ni++)
#pragma unroll
                    for (int qq = 0; qq < 4; qq++) acc[mi][ni][qq] = 0.f;
#pragma unroll 2
            for (int k16 = 0; k16 < 16; k16++) {
                const int kb = k16 * 32 + 4 * tg;
                unsigned ah[2][4], al[2][4], bh[4][2], bl[4][2];
#pragma unroll
                for (int mi = 0; mi < 2; mi++) {
                    const int rb = (32 * mw + 16 * mi + g) * ROWB;
                    ah[mi][0] = *(const unsigned*)(sAhi + rb + kb);
                    ah[mi][1] = *(const unsigned*)(sAhi + rb + 8 * ROWB + kb);
                    ah[mi][2] = *(const unsigned*)(sAhi + rb + kb + 16);
                    ah[mi][3] =
                        *(const unsigned*)(sAhi + rb + 8 * ROWB + kb + 16);
                    al[mi][0] = *(const unsigned*)(sAlo + rb + kb);
                    al[mi][1] = *(const unsigned*)(sAlo + rb + 8 * ROWB + kb);
                    al[mi][2] = *(const unsigned*)(sAlo + rb + kb + 16);
                    al[mi][3] =
                        *(const unsigned*)(sAlo + rb + 8 * ROWB + kb + 16);
                }
#pragma unroll
                for (int ni = 0; ni < 4; ni++) {
                    const int rb = ((4 * nh + ni) * 8 + g) * ROWB;
                    bh[ni][0] = *(const unsigned*)(sRhi + rb + kb);
                    bh[ni][1] = *(const unsigned*)(sRhi + rb + kb + 16);
                    bl[ni][0] = *(const unsigned*)(sRlo + rb + kb);
                    bl[ni][1] = *(const unsigned*)(sRlo + rb + kb + 16);
                }
#pragma unroll
                for (int mi = 0; mi < 2; mi++)
#pragma unroll
                    for (int ni = 0; ni < 4; ni++)
                        mma_bf16(acc[mi][ni], ah[mi], bh[ni]);
#pragma unroll
                for (int mi = 0; mi < 2; mi++)
#pragma unroll
                    for (int ni = 0; ni < 4; ni++)
                        mma_bf16(acc[mi][ni], ah[mi], bl[ni]);
#pragma unroll
                for (int mi = 0; mi < 2; mi++)
#pragma unroll
                    for (int ni = 0; ni < 4; ni++)
                        mma_bf16(acc[mi][ni], al[mi], bh[ni]);
            }
            // per-half join (disjoint sP rows overlay the half's own sRhi)
            {
                const int bid = 1 + nh;
                asm volatile("bar.sync %0, %1;" ::"r"(bid), "r"(128)
                             : "memory");
#pragma unroll
                for (int mi = 0; mi < 2; mi++) {
                    const int jr = 32 * mw + 16 * mi + g;
#pragma unroll
                    for (int ni = 0; ni < 4; ni++) {
                        const int bc = (4 * nh + ni) * 8 + 2 * tg;
                        sP[bc * 132 + jr] = acc[mi][ni][0];
                        sP[(bc + 1) * 132 + jr] = acc[mi][ni][1];
                        sP[bc * 132 + jr + 8] = acc[mi][ni][2];
                        sP[(bc + 1) * 132 + jr + 8] = acc[mi][ni][3];
                    }
                }
                asm volatile("bar.sync %0, %1;" ::"r"(bid), "r"(128)
                             : "memory");
                for (int i = tidh; i < 1024; i += 128) {
                    const int b = nh * 32 + (i >> 5), jq = (i & 31) * 4;
                    float4 v = *(const float4*)&sP[b * 132 + jq];
                    *(float4*)&g_part[(pbase + b) * 128 + jq] = v;
                }
            }
            // prefetch xin; local 8-CTA sync on this mt's partials
            xv = *(const float4*)&hid[(eb * TT + t) * RR + j0e];
            __syncthreads();
            if (tid == 0) {
                arrive(cnt1);
                waitctr(cnt1, c1Base + 8u * (unsigned)(t + 1), 0);
            }
            __syncthreads();
            // reduce own (eb, j0e) over the 8 k-splits of this mt
            const int jr0 = ks * 16 + ejq * 4;
#pragma unroll
            for (int s = 0; s < 8; s++) {
                float4 pa = *(const float4*)
                    &g_part[((s * 16 + mt) * 64 + eb) * 128 + jr0];
                q.x += pa.x; q.y += pa.y; q.z += pa.z; q.w += pa.w;
            }
        } else {
            if (tid == 0) arrive(cnt1);  // dummy t=0 arrival (keeps 2048/launch)
            xv = *(const float4*)&hid[(eb * TT + t) * RR + j0e];
        }
        // ---- epilogue ----
        float4 nr;
        nr.x = 0.5f * p0.x + 0.5f * tanhf(q.x + xv.x);
        nr.y = 0.5f * p0.y + 0.5f * tanhf(q.y + xv.y);
        nr.z = 0.5f * p0.z + 0.5f * tanhf(q.z + xv.z);
        nr.w = 0.5f * p0.w + 0.5f * tanhf(q.w + xv.w);
        p0 = nr;
        if (t == TT - 1) {
            *(float4*)&hid[(eb * TT + t) * RR + j0e] = nr;
        } else {
            pend = nr;
        }
        float h0 = __bfloat162float(__float2bfloat16_rn(nr.x));
        float h1 = __bfloat162float(__float2bfloat16_rn(nr.y));
        float h2 = __bfloat162float(__float2bfloat16_rn(nr.z));
        float h3 = __bfloat162float(__float2bfloat16_rn(nr.w));
        uint2 uh, ul;
        uh.x = pk(h0, h1);
        uh.y = pk(h2, h3);
        ul.x = pk(nr.x - h0, nr.y - h1);
        ul.y = pk(nr.z - h2, nr.w - h3);
        *(uint2*)&g_reshi[eb * RR + j0e] = uh;
        *(uint2*)&g_reslo[eb * RR + j0e] = ul;
        // global barrier: res ready for next step's staging (also orders
        // next step's g_part overwrite after this step's reads)
        __syncthreads();
        if (tid == 0) {
            arrive(&g_cnt);
            waitctr(&g_cnt, barBase + (unsigned)NCTA * (unsigned)(t + 1), 1);
        }
        __syncthreads();
    }

    // =========== Readout ===========
    if (cta < BB) {
        const float* res = &hid[(cta * TT + (TT - 1)) * RR];
        float acc[OO];
#pragma unroll
        for (int o = 0; o < OO; o++) acc[o] = 0.f;
        for (int r = tid; r < RR; r += NTHR) {
            float rv = res[r];
#pragma unroll
            for (int o = 0; o < OO; o++) acc[o] += rv * ow[r * OO + o];
        }
        float* red = (float*)sm8;
        __syncthreads();
#pragma unroll
        for (int o = 0; o < OO; o++) red[o * NTHR + tid] = acc[o];
        __syncthreads();
        for (int s2 = NTHR / 2; s2 > 0; s2 >>= 1) {
            if (tid < s2) {
#pragma unroll
                for (int o = 0; o < OO; o++)
                    red[o * NTHR + tid] += red[o * NTHR + tid + s2];
            }
            __syncthreads();
        }
        if (tid < OO) out[cta * OO + tid] = red[tid * NTHR] + ob[tid];
    }
}

extern "C" void kernel_launch(void* const* d_in, const int* in_sizes, int n_in,
                              void* d_out, int out_size) {
    const float* x = (const float*)d_in[0];
    const float* i2h = (const float*)d_in[1];
    const float* h2h = (const float*)d_in[2];
    const float* ow = (const float*)d_in[3];
    const float* ob = (const float*)d_in[4];
    float* out = (float*)d_out;
    float* hid = out + BB * OO;

    cudaFuncSetAttribute(esn_mma, cudaFuncAttributeMaxDynamicSharedMemorySize,
                         SM_TOTAL);
    esn_mma<<<NCTA, NTHR, SM_TOTAL>>>(x, i2h, h2h, ow, ob, out, hid);
}